// round 1
// baseline (speedup 1.0000x reference)
#include <cuda_runtime.h>
#include <cuda_bf16.h>
#include <math.h>

// Problem constants
#define BB 2
#define TT 2048
#define DM 2048
#define NH 32
#define NKV 8
#define HD 64
#define MROWS (BB*TT)          // 4096
#define QN (NH*HD)             // 2048
#define KN (NKV*HD)            // 512

// Scratch (device globals — allocation-free)
__device__ float g_q[MROWS*QN];
__device__ float g_k[MROWS*KN];
__device__ float g_v[MROWS*KN];
__device__ float g_att[MROWS*QN];

// ---------------------------------------------------------------------------
// NT SGEMM: C[M,N] = A[M,K] @ B[N,K]^T   (both row-major, K contiguous)
// BM=BN=128, BK=32, 256 threads, 8x8 microtile
// ---------------------------------------------------------------------------
#define BM 128
#define BN 128
#define BK 32
#define SPAD 132   // padded smem stride (132*4 = 528 = 33*16 -> float4 aligned)

__global__ __launch_bounds__(256) void sgemm_nt(const float* __restrict__ A,
                                                const float* __restrict__ B,
                                                float* __restrict__ C,
                                                int M, int N, int K) {
    __shared__ float As[BK][SPAD];
    __shared__ float Bs[BK][SPAD];
    const int bm = blockIdx.y * BM;
    const int bn = blockIdx.x * BN;
    const int tid = threadIdx.x;
    const int tr = tid >> 4;       // 0..15
    const int tc = tid & 15;       // 0..15

    float acc[8][8];
#pragma unroll
    for (int i = 0; i < 8; i++)
#pragma unroll
        for (int j = 0; j < 8; j++) acc[i][j] = 0.f;

    const int nT = K / BK;
    for (int t = 0; t < nT; ++t) {
        // Load tile: 128 rows x 32 cols each of A,B; store transposed [k][m]
#pragma unroll
        for (int i = 0; i < 4; i++) {
            int id = tid + i * 256;
            int row = id >> 3;       // 0..127
            int cv  = id & 7;        // 0..7 (float4 within 32 cols)
            float4 av = *(const float4*)&A[(size_t)(bm + row) * K + t * BK + cv * 4];
            As[cv*4+0][row] = av.x; As[cv*4+1][row] = av.y;
            As[cv*4+2][row] = av.z; As[cv*4+3][row] = av.w;
            float4 bv = *(const float4*)&B[(size_t)(bn + row) * K + t * BK + cv * 4];
            Bs[cv*4+0][row] = bv.x; Bs[cv*4+1][row] = bv.y;
            Bs[cv*4+2][row] = bv.z; Bs[cv*4+3][row] = bv.w;
        }
        __syncthreads();

#pragma unroll
        for (int k = 0; k < BK; k++) {
            float a[8], b[8];
            *(float4*)&a[0] = *(float4*)&As[k][tr * 4];
            *(float4*)&a[4] = *(float4*)&As[k][64 + tr * 4];
            *(float4*)&b[0] = *(float4*)&Bs[k][tc * 4];
            *(float4*)&b[4] = *(float4*)&Bs[k][64 + tc * 4];
#pragma unroll
            for (int i = 0; i < 8; i++)
#pragma unroll
                for (int j = 0; j < 8; j++)
                    acc[i][j] = fmaf(a[i], b[j], acc[i][j]);
        }
        __syncthreads();
    }

    // Epilogue
#pragma unroll
    for (int i = 0; i < 8; i++) {
        int row = bm + ((i < 4) ? (tr * 4 + i) : (64 + tr * 4 + (i - 4)));
        float4 v0 = make_float4(acc[i][0], acc[i][1], acc[i][2], acc[i][3]);
        float4 v1 = make_float4(acc[i][4], acc[i][5], acc[i][6], acc[i][7]);
        *(float4*)&C[(size_t)row * N + bn + tc * 4]      = v0;
        *(float4*)&C[(size_t)row * N + bn + 64 + tc * 4] = v1;
    }
}

// ---------------------------------------------------------------------------
// RoPE (in-place): x layout [B*T][nheads*64]
// ---------------------------------------------------------------------------
__global__ void rope_kernel(float* __restrict__ x, const float* __restrict__ cs,
                            const float* __restrict__ sn, int nheads, int total) {
    int idx = blockIdx.x * blockDim.x + threadIdx.x;
    if (idx >= total) return;
    int d  = idx & 31;                 // 0..31 (pair index)
    int h  = (idx >> 5) % nheads;
    int bt = idx / (32 * nheads);
    int t  = bt & (TT - 1);
    float* row = x + (size_t)bt * (nheads * HD) + h * HD;
    float x1 = row[d], x2 = row[d + 32];
    float c1 = cs[t * HD + d],      s1 = sn[t * HD + d];
    float c2 = cs[t * HD + d + 32], s2 = sn[t * HD + d + 32];
    row[d]      = x1 * c1 - x2 * s1;
    row[d + 32] = x2 * c2 + x1 * s2;
}

// ---------------------------------------------------------------------------
// Flash attention, fp32, causal, GQA (4 q-heads per kv-head)
// Block: 256 threads (16x16 microgrid, 4x4 per thread), q-tile 64, key-tile 64
// smem: Q[64][68], Kt[64][68] ([d][key]), V[64][68], P[64][68]  -> 69632 B
// ---------------------------------------------------------------------------
#define APAD 68

__global__ __launch_bounds__(256) void attn_kernel(const float* __restrict__ q,
                                                   const float* __restrict__ k,
                                                   const float* __restrict__ v,
                                                   float* __restrict__ o) {
    const int qt = blockIdx.x;       // 0..31
    const int h  = blockIdx.y;       // 0..31
    const int b  = blockIdx.z;       // 0..1
    const int kvh = h >> 2;
    const int q0 = qt * 64;

    extern __shared__ float sm[];
    float* Qs = sm;                    // [64][68]
    float* Ks = Qs + 64 * APAD;        // transposed: [d][key]
    float* Vs = Ks + 64 * APAD;        // [key][d]
    float* Ps = Vs + 64 * APAD;        // [q][key]

    const int tid = threadIdx.x;
    const int ty = tid >> 4;           // 0..15 -> q rows 4ty..4ty+3
    const int tx = tid & 15;           // 0..15 -> cols 4tx..4tx+3

    // Load Q tile
#pragma unroll
    for (int i = 0; i < 4; i++) {
        int id = tid + i * 256;
        int r = id >> 4, dv = id & 15;
        float4 qv = *(const float4*)&q[(size_t)(b * TT + q0 + r) * QN + h * HD + dv * 4];
        *(float4*)&Qs[r * APAD + dv * 4] = qv;
    }

    float m[4], l[4], oa[4][4];
#pragma unroll
    for (int i = 0; i < 4; i++) {
        m[i] = -INFINITY; l[i] = 0.f;
#pragma unroll
        for (int j = 0; j < 4; j++) oa[i][j] = 0.f;
    }

    const int nkt = qt + 1;
    for (int kt = 0; kt < nkt; ++kt) {
        const int k0 = kt * 64;
        __syncthreads();   // protect Ks/Vs from previous iteration readers
        // Load K (transposed) and V
#pragma unroll
        for (int i = 0; i < 4; i++) {
            int id = tid + i * 256;
            int c = id >> 4, dv = id & 15;
            size_t base = (size_t)(b * TT + k0 + c) * KN + kvh * HD + dv * 4;
            float4 k4 = *(const float4*)&k[base];
            Ks[(dv*4+0) * APAD + c] = k4.x;
            Ks[(dv*4+1) * APAD + c] = k4.y;
            Ks[(dv*4+2) * APAD + c] = k4.z;
            Ks[(dv*4+3) * APAD + c] = k4.w;
            float4 v4 = *(const float4*)&v[base];
            *(float4*)&Vs[c * APAD + dv * 4] = v4;
        }
        __syncthreads();

        // S = Q @ K^T  (4x4 per thread)
        float s[4][4];
#pragma unroll
        for (int i = 0; i < 4; i++)
#pragma unroll
            for (int j = 0; j < 4; j++) s[i][j] = 0.f;

#pragma unroll
        for (int d = 0; d < 64; d += 4) {
            float qf[4][4];
#pragma unroll
            for (int i = 0; i < 4; i++)
                *(float4*)qf[i] = *(float4*)&Qs[(ty * 4 + i) * APAD + d];
#pragma unroll
            for (int dd = 0; dd < 4; dd++) {
                float4 kf = *(float4*)&Ks[(d + dd) * APAD + tx * 4];
#pragma unroll
                for (int i = 0; i < 4; i++) {
                    s[i][0] = fmaf(qf[i][dd], kf.x, s[i][0]);
                    s[i][1] = fmaf(qf[i][dd], kf.y, s[i][1]);
                    s[i][2] = fmaf(qf[i][dd], kf.z, s[i][2]);
                    s[i][3] = fmaf(qf[i][dd], kf.w, s[i][3]);
                }
            }
        }

        // scale + causal mask
        const float scale = 0.125f;   // 1/sqrt(64)
#pragma unroll
        for (int i = 0; i < 4; i++) {
            int qg = q0 + ty * 4 + i;
#pragma unroll
            for (int j = 0; j < 4; j++) {
                int kg = k0 + tx * 4 + j;
                s[i][j] = (kg <= qg) ? s[i][j] * scale : -1e30f;
            }
        }

        // online softmax per row (row spread over 16 tx lanes)
#pragma unroll
        for (int i = 0; i < 4; i++) {
            float mx = fmaxf(fmaxf(s[i][0], s[i][1]), fmaxf(s[i][2], s[i][3]));
#pragma unroll
            for (int off = 8; off > 0; off >>= 1)
                mx = fmaxf(mx, __shfl_xor_sync(0xffffffffu, mx, off));
            float mn = fmaxf(m[i], mx);
            float p0 = __expf(s[i][0] - mn);
            float p1 = __expf(s[i][1] - mn);
            float p2 = __expf(s[i][2] - mn);
            float p3 = __expf(s[i][3] - mn);
            float rs = p0 + p1 + p2 + p3;
#pragma unroll
            for (int off = 8; off > 0; off >>= 1)
                rs += __shfl_xor_sync(0xffffffffu, rs, off);
            float alpha = __expf(m[i] - mn);
            l[i] = l[i] * alpha + rs;
            m[i] = mn;
#pragma unroll
            for (int j = 0; j < 4; j++) oa[i][j] *= alpha;
            float4 pv = make_float4(p0, p1, p2, p3);
            *(float4*)&Ps[(ty * 4 + i) * APAD + tx * 4] = pv;
        }
        __syncthreads();

        // O += P @ V
#pragma unroll
        for (int kk = 0; kk < 64; kk += 4) {
            float pf[4][4];
#pragma unroll
            for (int i = 0; i < 4; i++)
                *(float4*)pf[i] = *(float4*)&Ps[(ty * 4 + i) * APAD + kk];
#pragma unroll
            for (int dd = 0; dd < 4; dd++) {
                float4 vf = *(float4*)&Vs[(kk + dd) * APAD + tx * 4];
#pragma unroll
                for (int i = 0; i < 4; i++) {
                    oa[i][0] = fmaf(pf[i][dd], vf.x, oa[i][0]);
                    oa[i][1] = fmaf(pf[i][dd], vf.y, oa[i][1]);
                    oa[i][2] = fmaf(pf[i][dd], vf.z, oa[i][2]);
                    oa[i][3] = fmaf(pf[i][dd], vf.w, oa[i][3]);
                }
            }
        }
    }

    // Normalize + write out (attn output laid out [B*T][NH*HD])
#pragma unroll
    for (int i = 0; i < 4; i++) {
        float inv = 1.f / l[i];
        int row = b * TT + q0 + ty * 4 + i;
        float4 ov = make_float4(oa[i][0] * inv, oa[i][1] * inv,
                                oa[i][2] * inv, oa[i][3] * inv);
        *(float4*)&o[(size_t)row * QN + h * HD + tx * 4] = ov;
    }
}

// ---------------------------------------------------------------------------
// Launcher
// ---------------------------------------------------------------------------
extern "C" void kernel_launch(void* const* d_in, const int* in_sizes, int n_in,
                              void* d_out, int out_size) {
    const float* x   = (const float*)d_in[0];
    const float* cs  = (const float*)d_in[1];
    const float* sn  = (const float*)d_in[2];
    const float* Wq  = (const float*)d_in[3];
    const float* Wk  = (const float*)d_in[4];
    const float* Wv  = (const float*)d_in[5];
    const float* Wo  = (const float*)d_in[6];
    float* out = (float*)d_out;

    float *q_ptr, *k_ptr, *v_ptr, *att_ptr;
    cudaGetSymbolAddress((void**)&q_ptr,  g_q);
    cudaGetSymbolAddress((void**)&k_ptr,  g_k);
    cudaGetSymbolAddress((void**)&v_ptr,  g_v);
    cudaGetSymbolAddress((void**)&att_ptr, g_att);

    // QKV projections
    sgemm_nt<<<dim3(QN / BN, MROWS / BM), 256>>>(x, Wq, q_ptr, MROWS, QN, DM);
    sgemm_nt<<<dim3(KN / BN, MROWS / BM), 256>>>(x, Wk, k_ptr, MROWS, KN, DM);
    sgemm_nt<<<dim3(KN / BN, MROWS / BM), 256>>>(x, Wv, v_ptr, MROWS, KN, DM);

    // RoPE on q and k
    {
        int totq = BB * TT * NH * 32;
        rope_kernel<<<(totq + 255) / 256, 256>>>(q_ptr, cs, sn, NH, totq);
        int totk = BB * TT * NKV * 32;
        rope_kernel<<<(totk + 255) / 256, 256>>>(k_ptr, cs, sn, NKV, totk);
    }

    // Flash attention
    {
        int smem = 4 * 64 * APAD * sizeof(float);  // 69632 B
        cudaFuncSetAttribute(attn_kernel, cudaFuncAttributeMaxDynamicSharedMemorySize, smem);
        attn_kernel<<<dim3(TT / 64, NH, BB), 256, smem>>>(q_ptr, k_ptr, v_ptr, att_ptr);
    }

    // Output projection
    sgemm_nt<<<dim3(DM / BN, MROWS / BM), 256>>>(att_ptr, Wo, out, MROWS, DM, DM);
}

// round 3
// speedup vs baseline: 1.8549x; 1.8549x over previous
#include <cuda_runtime.h>
#include <cuda_bf16.h>
#include <math.h>
#include <stdint.h>

// Problem constants
#define BB 2
#define TT 2048
#define DM 2048
#define NH 32
#define NKV 8
#define HD 64
#define MROWS (BB*TT)          // 4096
#define QN (NH*HD)             // 2048
#define KN (NKV*HD)            // 512
#define GK DM                  // K dim of every GEMM = 2048

// Scratch (device globals — allocation-free)
__device__ float g_q[MROWS*QN];
__device__ float g_k[MROWS*KN];
__device__ float g_v[MROWS*KN];
__device__ float g_att[MROWS*QN];
// tf32-rounded copies
__device__ float g_xc[MROWS*DM];
__device__ float g_attc[MROWS*QN];
__device__ float g_wqc[QN*DM];
__device__ float g_wkc[KN*DM];
__device__ float g_wvc[KN*DM];
__device__ float g_woc[DM*QN];

__device__ __forceinline__ uint32_t smem_u32(const void* p) {
    uint32_t a;
    asm("{ .reg .u64 t; cvta.to.shared.u64 t, %1; cvt.u32.u64 %0, t; }"
        : "=r"(a) : "l"(p));
    return a;
}

// ---------------------------------------------------------------------------
// tf32 rounding pass (cvt.rna): fp32 -> tf32-valued fp32
// ---------------------------------------------------------------------------
__global__ void cvt_tf32(const float* __restrict__ in, float* __restrict__ out, int n4) {
    int i = blockIdx.x * blockDim.x + threadIdx.x;
    if (i >= n4) return;
    float4 v = ((const float4*)in)[i];
    uint32_t a, b, c, d;
    asm("cvt.rna.tf32.f32 %0, %1;" : "=r"(a) : "f"(v.x));
    asm("cvt.rna.tf32.f32 %0, %1;" : "=r"(b) : "f"(v.y));
    asm("cvt.rna.tf32.f32 %0, %1;" : "=r"(c) : "f"(v.z));
    asm("cvt.rna.tf32.f32 %0, %1;" : "=r"(d) : "f"(v.w));
    ((float4*)out)[i] = make_float4(__uint_as_float(a), __uint_as_float(b),
                                    __uint_as_float(c), __uint_as_float(d));
}

// ---------------------------------------------------------------------------
// mma.sync tf32 NT GEMM: C[M,N] = A[M,K] @ B[N,K]^T, K = 2048
// BM=BN=128, BK=32, 256 threads (8 warps, warp tile 64x32), double-buffered
// cp.async. Smem rows padded to 36 floats -> conflict-free fragment loads.
// ---------------------------------------------------------------------------
#define BM 128
#define BN 128
#define BK 32
#define NCH (GK/BK)            // 64
#define RST 36                 // smem row stride (floats); 36*4=144 B
#define TILEF (128*RST)        // floats per (A or B) tile = 4608
#define STAGEF (2*TILEF)       // floats per stage = 9216
#define GEMM_SMEM (2*STAGEF*4) // 73728 bytes

__device__ __forceinline__ void mma_tf32(float c[4], const uint32_t a[4],
                                         const uint32_t b[2]) {
    asm volatile(
        "mma.sync.aligned.m16n8k8.row.col.f32.tf32.tf32.f32 "
        "{%0,%1,%2,%3}, {%4,%5,%6,%7}, {%8,%9}, {%0,%1,%2,%3};"
        : "+f"(c[0]), "+f"(c[1]), "+f"(c[2]), "+f"(c[3])
        : "r"(a[0]), "r"(a[1]), "r"(a[2]), "r"(a[3]), "r"(b[0]), "r"(b[1]));
}

__global__ __launch_bounds__(256) void gemm_mma(const float* __restrict__ A,
                                                const float* __restrict__ B,
                                                float* __restrict__ C,
                                                int N) {
    extern __shared__ float sm[];
    const int tid = threadIdx.x;
    const int bm = blockIdx.y * BM;
    const int bn = blockIdx.x * BN;
    const int wid = tid >> 5, lane = tid & 31;
    const int g = lane >> 2, tg = lane & 3;
    const int wm = (wid >> 2) * 64;      // 0 or 64
    const int wn = (wid & 3) * 32;       // 0,32,64,96

    float c[4][4][4];
#pragma unroll
    for (int i = 0; i < 4; i++)
#pragma unroll
        for (int j = 0; j < 4; j++)
#pragma unroll
            for (int q = 0; q < 4; q++) c[i][j][q] = 0.f;

    const uint32_t sb = smem_u32(sm);

    auto load_chunk = [&](int kc, int s) {
        uint32_t base = sb + s * (STAGEF * 4);
#pragma unroll
        for (int j = 0; j < 8; j++) {
            int u = tid + j * 256;       // 0..2047
            uint32_t sa;
            const float* gp;
            if (u < 1024) {              // A tile: 128 rows x 32 floats
                int r = u >> 3, c16 = u & 7;
                sa = base + r * 144 + c16 * 16;
                gp = A + (size_t)(bm + r) * GK + kc * BK + c16 * 4;
            } else {                     // B tile
                int uu = u - 1024;
                int r = uu >> 3, c16 = uu & 7;
                sa = base + TILEF * 4 + r * 144 + c16 * 16;
                gp = B + (size_t)(bn + r) * GK + kc * BK + c16 * 4;
            }
            asm volatile("cp.async.cg.shared.global [%0], [%1], 16;"
                         :: "r"(sa), "l"(gp));
        }
        asm volatile("cp.async.commit_group;" ::: "memory");
    };

    load_chunk(0, 0);

    for (int t = 0; t < NCH; t++) {
        const int s = t & 1;
        if (t + 1 < NCH) {
            load_chunk(t + 1, (t + 1) & 1);
            asm volatile("cp.async.wait_group 1;" ::: "memory");
        } else {
            asm volatile("cp.async.wait_group 0;" ::: "memory");
        }
        __syncthreads();

        const float* Ab = sm + s * STAGEF;
        const float* Bb = Ab + TILEF;
#pragma unroll
        for (int ks = 0; ks < 4; ks++) {
            const int k0 = ks * 8;
            uint32_t af[4][4], bf[4][2];
#pragma unroll
            for (int tm = 0; tm < 4; tm++) {
                const int m0 = wm + tm * 16;
                af[tm][0] = __float_as_uint(Ab[(m0 + g)     * RST + k0 + tg]);
                af[tm][1] = __float_as_uint(Ab[(m0 + g + 8) * RST + k0 + tg]);
                af[tm][2] = __float_as_uint(Ab[(m0 + g)     * RST + k0 + tg + 4]);
                af[tm][3] = __float_as_uint(Ab[(m0 + g + 8) * RST + k0 + tg + 4]);
            }
#pragma unroll
            for (int tn = 0; tn < 4; tn++) {
                const int n0 = wn + tn * 8;
                bf[tn][0] = __float_as_uint(Bb[(n0 + g) * RST + k0 + tg]);
                bf[tn][1] = __float_as_uint(Bb[(n0 + g) * RST + k0 + tg + 4]);
            }
#pragma unroll
            for (int tm = 0; tm < 4; tm++)
#pragma unroll
                for (int tn = 0; tn < 4; tn++)
                    mma_tf32(c[tm][tn], af[tm], bf[tn]);
        }
        __syncthreads();
    }

    // Epilogue: direct register -> global (float2 per fragment half)
#pragma unroll
    for (int tm = 0; tm < 4; tm++) {
        const int row0 = bm + wm + tm * 16 + g;
#pragma unroll
        for (int tn = 0; tn < 4; tn++) {
            const int col = bn + wn + tn * 8 + tg * 2;
            *(float2*)&C[(size_t)row0 * N + col] =
                make_float2(c[tm][tn][0], c[tm][tn][1]);
            *(float2*)&C[(size_t)(row0 + 8) * N + col] =
                make_float2(c[tm][tn][2], c[tm][tn][3]);
        }
    }
}

// ---------------------------------------------------------------------------
// RoPE (in-place): x layout [B*T][nheads*64]
// ---------------------------------------------------------------------------
__global__ void rope_kernel(float* __restrict__ x, const float* __restrict__ cs,
                            const float* __restrict__ sn, int nheads, int total) {
    int idx = blockIdx.x * blockDim.x + threadIdx.x;
    if (idx >= total) return;
    int d  = idx & 31;
    int h  = (idx >> 5) % nheads;
    int bt = idx / (32 * nheads);
    int t  = bt & (TT - 1);
    float* row = x + (size_t)bt * (nheads * HD) + h * HD;
    float x1 = row[d], x2 = row[d + 32];
    float c1 = cs[t * HD + d],      s1 = sn[t * HD + d];
    float c2 = cs[t * HD + d + 32], s2 = sn[t * HD + d + 32];
    row[d]      = x1 * c1 - x2 * s1;
    row[d + 32] = x2 * c2 + x1 * s2;
}

// ---------------------------------------------------------------------------
// Flash attention, fp32, causal, GQA (R1-passing version, unchanged)
// ---------------------------------------------------------------------------
#define APAD 68

__global__ __launch_bounds__(256) void attn_kernel(const float* __restrict__ q,
                                                   const float* __restrict__ k,
                                                   const float* __restrict__ v,
                                                   float* __restrict__ o) {
    const int qt = blockIdx.x;
    const int h  = blockIdx.y;
    const int b  = blockIdx.z;
    const int kvh = h >> 2;
    const int q0 = qt * 64;

    extern __shared__ float sm[];
    float* Qs = sm;
    float* Ks = Qs + 64 * APAD;
    float* Vs = Ks + 64 * APAD;
    float* Ps = Vs + 64 * APAD;

    const int tid = threadIdx.x;
    const int ty = tid >> 4;
    const int tx = tid & 15;

#pragma unroll
    for (int i = 0; i < 4; i++) {
        int id = tid + i * 256;
        int r = id >> 4, dv = id & 15;
        float4 qv = *(const float4*)&q[(size_t)(b * TT + q0 + r) * QN + h * HD + dv * 4];
        *(float4*)&Qs[r * APAD + dv * 4] = qv;
    }

    float m[4], l[4], oa[4][4];
#pragma unroll
    for (int i = 0; i < 4; i++) {
        m[i] = -INFINITY; l[i] = 0.f;
#pragma unroll
        for (int j = 0; j < 4; j++) oa[i][j] = 0.f;
    }

    const int nkt = qt + 1;
    for (int kt = 0; kt < nkt; ++kt) {
        const int k0 = kt * 64;
        __syncthreads();
#pragma unroll
        for (int i = 0; i < 4; i++) {
            int id = tid + i * 256;
            int c = id >> 4, dv = id & 15;
            size_t base = (size_t)(b * TT + k0 + c) * KN + kvh * HD + dv * 4;
            float4 k4 = *(const float4*)&k[base];
            Ks[(dv*4+0) * APAD + c] = k4.x;
            Ks[(dv*4+1) * APAD + c] = k4.y;
            Ks[(dv*4+2) * APAD + c] = k4.z;
            Ks[(dv*4+3) * APAD + c] = k4.w;
            float4 v4 = *(const float4*)&v[base];
            *(float4*)&Vs[c * APAD + dv * 4] = v4;
        }
        __syncthreads();

        float s[4][4];
#pragma unroll
        for (int i = 0; i < 4; i++)
#pragma unroll
            for (int j = 0; j < 4; j++) s[i][j] = 0.f;

#pragma unroll
        for (int d = 0; d < 64; d += 4) {
            float qf[4][4];
#pragma unroll
            for (int i = 0; i < 4; i++)
                *(float4*)qf[i] = *(float4*)&Qs[(ty * 4 + i) * APAD + d];
#pragma unroll
            for (int dd = 0; dd < 4; dd++) {
                float4 kf = *(float4*)&Ks[(d + dd) * APAD + tx * 4];
#pragma unroll
                for (int i = 0; i < 4; i++) {
                    s[i][0] = fmaf(qf[i][dd], kf.x, s[i][0]);
                    s[i][1] = fmaf(qf[i][dd], kf.y, s[i][1]);
                    s[i][2] = fmaf(qf[i][dd], kf.z, s[i][2]);
                    s[i][3] = fmaf(qf[i][dd], kf.w, s[i][3]);
                }
            }
        }

        const float scale = 0.125f;
#pragma unroll
        for (int i = 0; i < 4; i++) {
            int qg = q0 + ty * 4 + i;
#pragma unroll
            for (int j = 0; j < 4; j++) {
                int kg = k0 + tx * 4 + j;
                s[i][j] = (kg <= qg) ? s[i][j] * scale : -1e30f;
            }
        }

#pragma unroll
        for (int i = 0; i < 4; i++) {
            float mx = fmaxf(fmaxf(s[i][0], s[i][1]), fmaxf(s[i][2], s[i][3]));
#pragma unroll
            for (int off = 8; off > 0; off >>= 1)
                mx = fmaxf(mx, __shfl_xor_sync(0xffffffffu, mx, off));
            float mn = fmaxf(m[i], mx);
            float p0 = __expf(s[i][0] - mn);
            float p1 = __expf(s[i][1] - mn);
            float p2 = __expf(s[i][2] - mn);
            float p3 = __expf(s[i][3] - mn);
            float rs = p0 + p1 + p2 + p3;
#pragma unroll
            for (int off = 8; off > 0; off >>= 1)
                rs += __shfl_xor_sync(0xffffffffu, rs, off);
            float alpha = __expf(m[i] - mn);
            l[i] = l[i] * alpha + rs;
            m[i] = mn;
#pragma unroll
            for (int j = 0; j < 4; j++) oa[i][j] *= alpha;
            float4 pv = make_float4(p0, p1, p2, p3);
            *(float4*)&Ps[(ty * 4 + i) * APAD + tx * 4] = pv;
        }
        __syncthreads();

#pragma unroll
        for (int kk = 0; kk < 64; kk += 4) {
            float pf[4][4];
#pragma unroll
            for (int i = 0; i < 4; i++)
                *(float4*)pf[i] = *(float4*)&Ps[(ty * 4 + i) * APAD + kk];
#pragma unroll
            for (int dd = 0; dd < 4; dd++) {
                float4 vf = *(float4*)&Vs[(kk + dd) * APAD + tx * 4];
#pragma unroll
                for (int i = 0; i < 4; i++) {
                    oa[i][0] = fmaf(pf[i][dd], vf.x, oa[i][0]);
                    oa[i][1] = fmaf(pf[i][dd], vf.y, oa[i][1]);
                    oa[i][2] = fmaf(pf[i][dd], vf.z, oa[i][2]);
                    oa[i][3] = fmaf(pf[i][dd], vf.w, oa[i][3]);
                }
            }
        }
    }

#pragma unroll
    for (int i = 0; i < 4; i++) {
        float inv = 1.f / l[i];
        int row = b * TT + q0 + ty * 4 + i;
        float4 ov = make_float4(oa[i][0] * inv, oa[i][1] * inv,
                                oa[i][2] * inv, oa[i][3] * inv);
        *(float4*)&o[(size_t)row * QN + h * HD + tx * 4] = ov;
    }
}

// ---------------------------------------------------------------------------
// Launcher
// ---------------------------------------------------------------------------
extern "C" void kernel_launch(void* const* d_in, const int* in_sizes, int n_in,
                              void* d_out, int out_size) {
    const float* x   = (const float*)d_in[0];
    const float* cs  = (const float*)d_in[1];
    const float* sn  = (const float*)d_in[2];
    const float* Wq  = (const float*)d_in[3];
    const float* Wk  = (const float*)d_in[4];
    const float* Wv  = (const float*)d_in[5];
    const float* Wo  = (const float*)d_in[6];
    float* out = (float*)d_out;

    float *q_ptr, *k_ptr, *v_ptr, *att_ptr;
    float *xc, *attc, *wqc, *wkc, *wvc, *woc;
    cudaGetSymbolAddress((void**)&q_ptr,  g_q);
    cudaGetSymbolAddress((void**)&k_ptr,  g_k);
    cudaGetSymbolAddress((void**)&v_ptr,  g_v);
    cudaGetSymbolAddress((void**)&att_ptr, g_att);
    cudaGetSymbolAddress((void**)&xc,   g_xc);
    cudaGetSymbolAddress((void**)&attc, g_attc);
    cudaGetSymbolAddress((void**)&wqc,  g_wqc);
    cudaGetSymbolAddress((void**)&wkc,  g_wkc);
    cudaGetSymbolAddress((void**)&wvc,  g_wvc);
    cudaGetSymbolAddress((void**)&woc,  g_woc);

    cudaFuncSetAttribute(gemm_mma, cudaFuncAttributeMaxDynamicSharedMemorySize, GEMM_SMEM);

    // tf32-round inputs
    {
        int n4;
        n4 = MROWS*DM/4;  cvt_tf32<<<(n4+255)/256, 256>>>(x,  xc,  n4);
        n4 = QN*DM/4;     cvt_tf32<<<(n4+255)/256, 256>>>(Wq, wqc, n4);
        n4 = KN*DM/4;     cvt_tf32<<<(n4+255)/256, 256>>>(Wk, wkc, n4);
        n4 = KN*DM/4;     cvt_tf32<<<(n4+255)/256, 256>>>(Wv, wvc, n4);
        n4 = DM*QN/4;     cvt_tf32<<<(n4+255)/256, 256>>>(Wo, woc, n4);
    }

    // QKV projections (tensor-core tf32 mma.sync)
    gemm_mma<<<dim3(QN/BN, MROWS/BM), 256, GEMM_SMEM>>>(xc, wqc, q_ptr, QN);
    gemm_mma<<<dim3(KN/BN, MROWS/BM), 256, GEMM_SMEM>>>(xc, wkc, k_ptr, KN);
    gemm_mma<<<dim3(KN/BN, MROWS/BM), 256, GEMM_SMEM>>>(xc, wvc, v_ptr, KN);

    // RoPE on q and k
    {
        int totq = BB * TT * NH * 32;
        rope_kernel<<<(totq + 255) / 256, 256>>>(q_ptr, cs, sn, NH, totq);
        int totk = BB * TT * NKV * 32;
        rope_kernel<<<(totk + 255) / 256, 256>>>(k_ptr, cs, sn, NKV, totk);
    }

    // Flash attention (SIMT fp32)
    {
        int smem = 4 * 64 * APAD * sizeof(float);
        cudaFuncSetAttribute(attn_kernel, cudaFuncAttributeMaxDynamicSharedMemorySize, smem);
        attn_kernel<<<dim3(TT / 64, NH, BB), 256, smem>>>(q_ptr, k_ptr, v_ptr, att_ptr);
    }

    // Output projection (tensor-core tf32 mma.sync)
    {
        int n4 = MROWS*QN/4;
        cvt_tf32<<<(n4+255)/256, 256>>>(att_ptr, attc, n4);
        gemm_mma<<<dim3(DM/BN, MROWS/BM), 256, GEMM_SMEM>>>(attc, woc, out, DM);
    }
}

// round 4
// speedup vs baseline: 3.1756x; 1.7120x over previous
#include <cuda_runtime.h>
#include <cuda_bf16.h>
#include <math.h>
#include <stdint.h>

// Problem constants
#define BB 2
#define TT 2048
#define DM 2048
#define NH 32
#define NKV 8
#define HD 64
#define MROWS (BB*TT)          // 4096
#define QN (NH*HD)             // 2048
#define KN (NKV*HD)            // 512
#define GK DM                  // K dim of every GEMM = 2048

// Scratch (device globals — allocation-free)
__device__ float g_q[MROWS*QN];
__device__ float g_k[MROWS*KN];
__device__ float g_v[MROWS*KN];
__device__ float g_att[MROWS*QN];
// tf32-rounded copies
__device__ float g_xc[MROWS*DM];
__device__ float g_attc[MROWS*QN];
__device__ float g_wqc[QN*DM];
__device__ float g_wkc[KN*DM];
__device__ float g_wvc[KN*DM];
__device__ float g_woc[DM*QN];

__device__ __forceinline__ uint32_t smem_u32(const void* p) {
    uint32_t a;
    asm("{ .reg .u64 t; cvta.to.shared.u64 t, %1; cvt.u32.u64 %0, t; }"
        : "=r"(a) : "l"(p));
    return a;
}
__device__ __forceinline__ float rna(float x) {
    uint32_t u;
    asm("cvt.rna.tf32.f32 %0, %1;" : "=r"(u) : "f"(x));
    return __uint_as_float(u);
}
__device__ __forceinline__ void mma_tf32(float c[4], const uint32_t a[4],
                                         const uint32_t b[2]) {
    asm volatile(
        "mma.sync.aligned.m16n8k8.row.col.f32.tf32.tf32.f32 "
        "{%0,%1,%2,%3}, {%4,%5,%6,%7}, {%8,%9}, {%0,%1,%2,%3};"
        : "+f"(c[0]), "+f"(c[1]), "+f"(c[2]), "+f"(c[3])
        : "r"(a[0]), "r"(a[1]), "r"(a[2]), "r"(a[3]), "r"(b[0]), "r"(b[1]));
}

// ---------------------------------------------------------------------------
// tf32 rounding pass
// ---------------------------------------------------------------------------
__global__ void cvt_tf32(const float* __restrict__ in, float* __restrict__ out, int n4) {
    int i = blockIdx.x * blockDim.x + threadIdx.x;
    if (i >= n4) return;
    float4 v = ((const float4*)in)[i];
    ((float4*)out)[i] = make_float4(rna(v.x), rna(v.y), rna(v.z), rna(v.w));
}

// ---------------------------------------------------------------------------
// mma.sync tf32 NT GEMM (unchanged from R3-passing version)
// ---------------------------------------------------------------------------
#define BM 128
#define BN 128
#define BK 32
#define NCH (GK/BK)
#define RST 36
#define TILEF (128*RST)
#define STAGEF (2*TILEF)
#define GEMM_SMEM (2*STAGEF*4)

__global__ __launch_bounds__(256) void gemm_mma(const float* __restrict__ A,
                                                const float* __restrict__ B,
                                                float* __restrict__ C,
                                                int N) {
    extern __shared__ float sm[];
    const int tid = threadIdx.x;
    const int bm = blockIdx.y * BM;
    const int bn = blockIdx.x * BN;
    const int wid = tid >> 5, lane = tid & 31;
    const int g = lane >> 2, tg = lane & 3;
    const int wm = (wid >> 2) * 64;
    const int wn = (wid & 3) * 32;

    float c[4][4][4];
#pragma unroll
    for (int i = 0; i < 4; i++)
#pragma unroll
        for (int j = 0; j < 4; j++)
#pragma unroll
            for (int q = 0; q < 4; q++) c[i][j][q] = 0.f;

    const uint32_t sb = smem_u32(sm);

    auto load_chunk = [&](int kc, int s) {
        uint32_t base = sb + s * (STAGEF * 4);
#pragma unroll
        for (int j = 0; j < 8; j++) {
            int u = tid + j * 256;
            uint32_t sa;
            const float* gp;
            if (u < 1024) {
                int r = u >> 3, c16 = u & 7;
                sa = base + r * 144 + c16 * 16;
                gp = A + (size_t)(bm + r) * GK + kc * BK + c16 * 4;
            } else {
                int uu = u - 1024;
                int r = uu >> 3, c16 = uu & 7;
                sa = base + TILEF * 4 + r * 144 + c16 * 16;
                gp = B + (size_t)(bn + r) * GK + kc * BK + c16 * 4;
            }
            asm volatile("cp.async.cg.shared.global [%0], [%1], 16;"
                         :: "r"(sa), "l"(gp));
        }
        asm volatile("cp.async.commit_group;" ::: "memory");
    };

    load_chunk(0, 0);

    for (int t = 0; t < NCH; t++) {
        const int s = t & 1;
        if (t + 1 < NCH) {
            load_chunk(t + 1, (t + 1) & 1);
            asm volatile("cp.async.wait_group 1;" ::: "memory");
        } else {
            asm volatile("cp.async.wait_group 0;" ::: "memory");
        }
        __syncthreads();

        const float* Ab = sm + s * STAGEF;
        const float* Bb = Ab + TILEF;
#pragma unroll
        for (int ks = 0; ks < 4; ks++) {
            const int k0 = ks * 8;
            uint32_t af[4][4], bf[4][2];
#pragma unroll
            for (int tm = 0; tm < 4; tm++) {
                const int m0 = wm + tm * 16;
                af[tm][0] = __float_as_uint(Ab[(m0 + g)     * RST + k0 + tg]);
                af[tm][1] = __float_as_uint(Ab[(m0 + g + 8) * RST + k0 + tg]);
                af[tm][2] = __float_as_uint(Ab[(m0 + g)     * RST + k0 + tg + 4]);
                af[tm][3] = __float_as_uint(Ab[(m0 + g + 8) * RST + k0 + tg + 4]);
            }
#pragma unroll
            for (int tn = 0; tn < 4; tn++) {
                const int n0 = wn + tn * 8;
                bf[tn][0] = __float_as_uint(Bb[(n0 + g) * RST + k0 + tg]);
                bf[tn][1] = __float_as_uint(Bb[(n0 + g) * RST + k0 + tg + 4]);
            }
#pragma unroll
            for (int tm = 0; tm < 4; tm++)
#pragma unroll
                for (int tn = 0; tn < 4; tn++)
                    mma_tf32(c[tm][tn], af[tm], bf[tn]);
        }
        __syncthreads();
    }

#pragma unroll
    for (int tm = 0; tm < 4; tm++) {
        const int row0 = bm + wm + tm * 16 + g;
#pragma unroll
        for (int tn = 0; tn < 4; tn++) {
            const int col = bn + wn + tn * 8 + tg * 2;
            *(float2*)&C[(size_t)row0 * N + col] =
                make_float2(c[tm][tn][0], c[tm][tn][1]);
            *(float2*)&C[(size_t)(row0 + 8) * N + col] =
                make_float2(c[tm][tn][2], c[tm][tn][3]);
        }
    }
}

// ---------------------------------------------------------------------------
// RoPE (in-place)
// ---------------------------------------------------------------------------
__global__ void rope_kernel(float* __restrict__ x, const float* __restrict__ cs,
                            const float* __restrict__ sn, int nheads, int total) {
    int idx = blockIdx.x * blockDim.x + threadIdx.x;
    if (idx >= total) return;
    int d  = idx & 31;
    int h  = (idx >> 5) % nheads;
    int bt = idx / (32 * nheads);
    int t  = bt & (TT - 1);
    float* row = x + (size_t)bt * (nheads * HD) + h * HD;
    float x1 = row[d], x2 = row[d + 32];
    float c1 = cs[t * HD + d],      s1 = sn[t * HD + d];
    float c2 = cs[t * HD + d + 32], s2 = sn[t * HD + d + 32];
    row[d]      = x1 * c1 - x2 * s1;
    row[d + 32] = x2 * c2 + x1 * s2;
}

// ---------------------------------------------------------------------------
// Tensor-core flash attention (tf32 mma.sync), causal, GQA
// Block: 128 threads (4 warps x 16 q-rows). Tiles: 64 q x 64 kv, HD=64.
// Smem: Ks[64][68] (also Q staging), Vs[64][72], Ps[64][68] = 53248 B.
// ---------------------------------------------------------------------------
#define KST 68
#define VST 72
#define ATTN_SMEM ((64*KST + 64*VST + 64*KST) * 4)

__global__ __launch_bounds__(128) void attn_tc(const float* __restrict__ q,
                                               const float* __restrict__ k,
                                               const float* __restrict__ v,
                                               float* __restrict__ o) {
    const int qt = (int)gridDim.x - 1 - (int)blockIdx.x;  // heavy CTAs first
    const int h  = blockIdx.y;
    const int b  = blockIdx.z;
    const int kvh = h >> 2;
    const int q0 = qt * 64;

    extern __shared__ float sm[];
    float* Ks = sm;                    // [64][KST]
    float* Vs = Ks + 64 * KST;         // [64][VST]
    float* Ps = Vs + 64 * VST;         // [64][KST]

    const int tid = threadIdx.x;
    const int w = tid >> 5, lane = tid & 31;
    const int g = lane >> 2, tg = lane & 3;
    const int wq0 = w * 16;

    // ---- Stage Q (tf32-rounded) into Ks region, then preload A-fragments ----
#pragma unroll
    for (int j = 0; j < 8; j++) {
        int i = tid + j * 128;           // 0..1023 float4 units
        int r = i >> 4, c4 = i & 15;
        float4 qv = *(const float4*)&q[(size_t)(b * TT + q0 + r) * QN + h * HD + c4 * 4];
        *(float4*)&Ks[r * KST + c4 * 4] =
            make_float4(rna(qv.x), rna(qv.y), rna(qv.z), rna(qv.w));
    }
    __syncthreads();

    uint32_t qf[8][4];
#pragma unroll
    for (int ks = 0; ks < 8; ks++) {
        const int k0 = ks * 8;
        qf[ks][0] = __float_as_uint(Ks[(wq0 + g)     * KST + k0 + tg]);
        qf[ks][1] = __float_as_uint(Ks[(wq0 + g + 8) * KST + k0 + tg]);
        qf[ks][2] = __float_as_uint(Ks[(wq0 + g)     * KST + k0 + tg + 4]);
        qf[ks][3] = __float_as_uint(Ks[(wq0 + g + 8) * KST + k0 + tg + 4]);
    }

    float oacc[8][4];
#pragma unroll
    for (int nt = 0; nt < 8; nt++)
#pragma unroll
        for (int qq = 0; qq < 4; qq++) oacc[nt][qq] = 0.f;
    float m0 = -INFINITY, m1 = -INFINITY, l0 = 0.f, l1 = 0.f;

    for (int kt = 0; kt <= qt; ++kt) {
        __syncthreads();   // all warps done with Ks/Vs (and Q frags on kt==0)
        const int k0g = kt * 64;
        // ---- Stage K,V tiles (tf32-rounded) ----
#pragma unroll
        for (int j = 0; j < 8; j++) {
            int i = tid + j * 128;
            int r = i >> 4, c4 = i & 15;
            size_t base = (size_t)(b * TT + k0g + r) * KN + kvh * HD + c4 * 4;
            float4 kv4 = *(const float4*)&k[base];
            float4 vv4 = *(const float4*)&v[base];
            *(float4*)&Ks[r * KST + c4 * 4] =
                make_float4(rna(kv4.x), rna(kv4.y), rna(kv4.z), rna(kv4.w));
            *(float4*)&Vs[r * VST + c4 * 4] =
                make_float4(rna(vv4.x), rna(vv4.y), rna(vv4.z), rna(vv4.w));
        }
        __syncthreads();

        // ---- S = Q @ K^T ----
        float sc[8][4];
#pragma unroll
        for (int nt = 0; nt < 8; nt++)
#pragma unroll
            for (int qq = 0; qq < 4; qq++) sc[nt][qq] = 0.f;

#pragma unroll
        for (int ks = 0; ks < 8; ks++) {
            const int k0 = ks * 8;
            uint32_t bf[8][2];
#pragma unroll
            for (int nt = 0; nt < 8; nt++) {
                bf[nt][0] = __float_as_uint(Ks[(nt * 8 + g) * KST + k0 + tg]);
                bf[nt][1] = __float_as_uint(Ks[(nt * 8 + g) * KST + k0 + tg + 4]);
            }
#pragma unroll
            for (int nt = 0; nt < 8; nt++)
                mma_tf32(sc[nt], qf[ks], bf[nt]);
        }

        // ---- scale + causal mask (diagonal tile only) ----
        const float scale = 0.125f;
        if (kt == qt) {
            const int r0 = wq0 + g, r1 = wq0 + g + 8;
#pragma unroll
            for (int nt = 0; nt < 8; nt++) {
                int c0 = nt * 8 + 2 * tg, c1 = c0 + 1;
                sc[nt][0] = (c0 <= r0) ? sc[nt][0] * scale : -1e30f;
                sc[nt][1] = (c1 <= r0) ? sc[nt][1] * scale : -1e30f;
                sc[nt][2] = (c0 <= r1) ? sc[nt][2] * scale : -1e30f;
                sc[nt][3] = (c1 <= r1) ? sc[nt][3] * scale : -1e30f;
            }
        } else {
#pragma unroll
            for (int nt = 0; nt < 8; nt++)
#pragma unroll
                for (int qq = 0; qq < 4; qq++) sc[nt][qq] *= scale;
        }

        // ---- online softmax (rows g and g+8; reduce over tg lanes) ----
        float mx0 = -INFINITY, mx1 = -INFINITY;
#pragma unroll
        for (int nt = 0; nt < 8; nt++) {
            mx0 = fmaxf(mx0, fmaxf(sc[nt][0], sc[nt][1]));
            mx1 = fmaxf(mx1, fmaxf(sc[nt][2], sc[nt][3]));
        }
        mx0 = fmaxf(mx0, __shfl_xor_sync(0xffffffffu, mx0, 1));
        mx0 = fmaxf(mx0, __shfl_xor_sync(0xffffffffu, mx0, 2));
        mx1 = fmaxf(mx1, __shfl_xor_sync(0xffffffffu, mx1, 1));
        mx1 = fmaxf(mx1, __shfl_xor_sync(0xffffffffu, mx1, 2));

        float mn0 = fmaxf(m0, mx0), mn1 = fmaxf(m1, mx1);
        float al0 = __expf(m0 - mn0), al1 = __expf(m1 - mn1);
        m0 = mn0; m1 = mn1;
        float rs0 = 0.f, rs1 = 0.f;
#pragma unroll
        for (int nt = 0; nt < 8; nt++) {
            sc[nt][0] = __expf(sc[nt][0] - mn0);
            sc[nt][1] = __expf(sc[nt][1] - mn0);
            sc[nt][2] = __expf(sc[nt][2] - mn1);
            sc[nt][3] = __expf(sc[nt][3] - mn1);
            rs0 += sc[nt][0] + sc[nt][1];
            rs1 += sc[nt][2] + sc[nt][3];
        }
        rs0 += __shfl_xor_sync(0xffffffffu, rs0, 1);
        rs0 += __shfl_xor_sync(0xffffffffu, rs0, 2);
        rs1 += __shfl_xor_sync(0xffffffffu, rs1, 1);
        rs1 += __shfl_xor_sync(0xffffffffu, rs1, 2);
        l0 = l0 * al0 + rs0;
        l1 = l1 * al1 + rs1;
#pragma unroll
        for (int nt = 0; nt < 8; nt++) {
            oacc[nt][0] *= al0; oacc[nt][1] *= al0;
            oacc[nt][2] *= al1; oacc[nt][3] *= al1;
        }

        // ---- P to smem (warp-private rows), reload as A-frags ----
#pragma unroll
        for (int nt = 0; nt < 8; nt++) {
            *(float2*)&Ps[(wq0 + g)     * KST + nt * 8 + 2 * tg] =
                make_float2(sc[nt][0], sc[nt][1]);
            *(float2*)&Ps[(wq0 + g + 8) * KST + nt * 8 + 2 * tg] =
                make_float2(sc[nt][2], sc[nt][3]);
        }
        __syncwarp();

        // ---- O += P @ V ----
#pragma unroll
        for (int ks = 0; ks < 8; ks++) {
            const int kk = ks * 8;
            uint32_t af[4];
            af[0] = __float_as_uint(Ps[(wq0 + g)     * KST + kk + tg]);
            af[1] = __float_as_uint(Ps[(wq0 + g + 8) * KST + kk + tg]);
            af[2] = __float_as_uint(Ps[(wq0 + g)     * KST + kk + tg + 4]);
            af[3] = __float_as_uint(Ps[(wq0 + g + 8) * KST + kk + tg + 4]);
            uint32_t bf[8][2];
#pragma unroll
            for (int nt = 0; nt < 8; nt++) {
                bf[nt][0] = __float_as_uint(Vs[(kk + tg)     * VST + nt * 8 + g]);
                bf[nt][1] = __float_as_uint(Vs[(kk + tg + 4) * VST + nt * 8 + g]);
            }
#pragma unroll
            for (int nt = 0; nt < 8; nt++)
                mma_tf32(oacc[nt], af, bf[nt]);
        }
    }

    // ---- normalize + write ----
    const float inv0 = 1.f / l0, inv1 = 1.f / l1;
    const int row0 = b * TT + q0 + wq0 + g;
#pragma unroll
    for (int nt = 0; nt < 8; nt++) {
        const int col = h * HD + nt * 8 + 2 * tg;
        *(float2*)&o[(size_t)row0 * QN + col] =
            make_float2(oacc[nt][0] * inv0, oacc[nt][1] * inv0);
        *(float2*)&o[(size_t)(row0 + 8) * QN + col] =
            make_float2(oacc[nt][2] * inv1, oacc[nt][3] * inv1);
    }
}

// ---------------------------------------------------------------------------
// Launcher
// ---------------------------------------------------------------------------
extern "C" void kernel_launch(void* const* d_in, const int* in_sizes, int n_in,
                              void* d_out, int out_size) {
    const float* x   = (const float*)d_in[0];
    const float* cs  = (const float*)d_in[1];
    const float* sn  = (const float*)d_in[2];
    const float* Wq  = (const float*)d_in[3];
    const float* Wk  = (const float*)d_in[4];
    const float* Wv  = (const float*)d_in[5];
    const float* Wo  = (const float*)d_in[6];
    float* out = (float*)d_out;

    float *q_ptr, *k_ptr, *v_ptr, *att_ptr;
    float *xc, *attc, *wqc, *wkc, *wvc, *woc;
    cudaGetSymbolAddress((void**)&q_ptr,  g_q);
    cudaGetSymbolAddress((void**)&k_ptr,  g_k);
    cudaGetSymbolAddress((void**)&v_ptr,  g_v);
    cudaGetSymbolAddress((void**)&att_ptr, g_att);
    cudaGetSymbolAddress((void**)&xc,   g_xc);
    cudaGetSymbolAddress((void**)&attc, g_attc);
    cudaGetSymbolAddress((void**)&wqc,  g_wqc);
    cudaGetSymbolAddress((void**)&wkc,  g_wkc);
    cudaGetSymbolAddress((void**)&wvc,  g_wvc);
    cudaGetSymbolAddress((void**)&woc,  g_woc);

    cudaFuncSetAttribute(gemm_mma, cudaFuncAttributeMaxDynamicSharedMemorySize, GEMM_SMEM);
    cudaFuncSetAttribute(attn_tc,  cudaFuncAttributeMaxDynamicSharedMemorySize, ATTN_SMEM);

    // tf32-round inputs
    {
        int n4;
        n4 = MROWS*DM/4;  cvt_tf32<<<(n4+255)/256, 256>>>(x,  xc,  n4);
        n4 = QN*DM/4;     cvt_tf32<<<(n4+255)/256, 256>>>(Wq, wqc, n4);
        n4 = KN*DM/4;     cvt_tf32<<<(n4+255)/256, 256>>>(Wk, wkc, n4);
        n4 = KN*DM/4;     cvt_tf32<<<(n4+255)/256, 256>>>(Wv, wvc, n4);
        n4 = DM*QN/4;     cvt_tf32<<<(n4+255)/256, 256>>>(Wo, woc, n4);
    }

    // QKV projections
    gemm_mma<<<dim3(QN/BN, MROWS/BM), 256, GEMM_SMEM>>>(xc, wqc, q_ptr, QN);
    gemm_mma<<<dim3(KN/BN, MROWS/BM), 256, GEMM_SMEM>>>(xc, wkc, k_ptr, KN);
    gemm_mma<<<dim3(KN/BN, MROWS/BM), 256, GEMM_SMEM>>>(xc, wvc, v_ptr, KN);

    // RoPE on q and k
    {
        int totq = BB * TT * NH * 32;
        rope_kernel<<<(totq + 255) / 256, 256>>>(q_ptr, cs, sn, NH, totq);
        int totk = BB * TT * NKV * 32;
        rope_kernel<<<(totk + 255) / 256, 256>>>(k_ptr, cs, sn, NKV, totk);
    }

    // Tensor-core flash attention
    attn_tc<<<dim3(TT / 64, NH, BB), 128, ATTN_SMEM>>>(q_ptr, k_ptr, v_ptr, att_ptr);

    // Output projection
    {
        int n4 = MROWS*QN/4;
        cvt_tf32<<<(n4+255)/256, 256>>>(att_ptr, attc, n4);
        gemm_mma<<<dim3(DM/BN, MROWS/BM), 256, GEMM_SMEM>>>(attc, woc, out, DM);
    }
}

// round 5
// speedup vs baseline: 3.2498x; 1.0234x over previous
#include <cuda_runtime.h>
#include <cuda_bf16.h>
#include <math.h>
#include <stdint.h>

// Problem constants
#define BB 2
#define TT 2048
#define DM 2048
#define NH 32
#define NKV 8
#define HD 64
#define MROWS (BB*TT)          // 4096
#define QN (NH*HD)             // 2048
#define KN (NKV*HD)            // 512
#define GK DM                  // K dim of every GEMM = 2048

// Scratch (device globals — allocation-free)
__device__ float g_q[MROWS*QN];
__device__ float g_k[MROWS*KN];
__device__ float g_v[MROWS*KN];
__device__ float g_att[MROWS*QN];

__device__ __forceinline__ float rna(float x) {
    uint32_t u;
    asm("cvt.rna.tf32.f32 %0, %1;" : "=r"(u) : "f"(x));
    return __uint_as_float(u);
}
__device__ __forceinline__ uint32_t rnau(float x) {
    uint32_t u;
    asm("cvt.rna.tf32.f32 %0, %1;" : "=r"(u) : "f"(x));
    return u;
}
__device__ __forceinline__ uint32_t smem_u32(const void* p) {
    uint32_t a;
    asm("{ .reg .u64 t; cvta.to.shared.u64 t, %1; cvt.u32.u64 %0, t; }"
        : "=r"(a) : "l"(p));
    return a;
}
__device__ __forceinline__ void mma_tf32(float c[4], const uint32_t a[4],
                                         const uint32_t b[2]) {
    asm volatile(
        "mma.sync.aligned.m16n8k8.row.col.f32.tf32.tf32.f32 "
        "{%0,%1,%2,%3}, {%4,%5,%6,%7}, {%8,%9}, {%0,%1,%2,%3};"
        : "+f"(c[0]), "+f"(c[1]), "+f"(c[2]), "+f"(c[3])
        : "r"(a[0]), "r"(a[1]), "r"(a[2]), "r"(a[3]), "r"(b[0]), "r"(b[1]));
}

// ---------------------------------------------------------------------------
// mma.sync tf32 NT GEMM, BM=128, BN=256, BK=32, 256 threads.
// 8 warps as 2x4 grid of 64x64 warp tiles. rna applied at fragment load.
// Segmented-N: columns [0,nb1) -> B0/C0(ld0); [nb1,nb2) -> B1/C1(512);
//              [nb2,...) -> B2/C2(512).  (Fused QKV; O-proj uses seg 0 only.)
// ---------------------------------------------------------------------------
#define BM 128
#define BN 256
#define BK 32
#define NCH (GK/BK)            // 64
#define RST 36                 // padded row stride in floats
#define ATILEB (128*RST*4)     // 18432 B
#define STAGEB ((128+256)*RST*4)  // 55296 B
#define GEMM_SMEM (2*STAGEB)   // 110592 B

__global__ __launch_bounds__(256, 1) void gemm_mma(
    const float* __restrict__ A,
    const float* __restrict__ B0, const float* __restrict__ B1,
    const float* __restrict__ B2,
    float* __restrict__ C0, float* __restrict__ C1, float* __restrict__ C2,
    int nb1, int nb2, int ld0) {
    extern __shared__ float sm[];
    const int tid = threadIdx.x;
    const int bm = blockIdx.y * BM;
    const int bn = blockIdx.x * BN;
    const int wid = tid >> 5, lane = tid & 31;
    const int g = lane >> 2, tg = lane & 3;
    const int wm = (wid >> 2) * 64;      // 0 or 64
    const int wn = (wid & 3) * 64;       // 0,64,128,192

    // Segment select (BN=256 divides all segment boundaries)
    const float* Bp; float* Cp; int nb, ldc;
    if (bn < nb1)      { Bp = B0; Cp = C0; nb = bn;       ldc = ld0; }
    else if (bn < nb2) { Bp = B1; Cp = C1; nb = bn - nb1; ldc = 512; }
    else               { Bp = B2; Cp = C2; nb = bn - nb2; ldc = 512; }

    float c[4][8][4];
#pragma unroll
    for (int i = 0; i < 4; i++)
#pragma unroll
        for (int j = 0; j < 8; j++)
#pragma unroll
            for (int q = 0; q < 4; q++) c[i][j][q] = 0.f;

    const uint32_t sb = smem_u32(sm);

    auto load_chunk = [&](int kc, int s) {
        uint32_t base = sb + s * STAGEB;
#pragma unroll
        for (int j = 0; j < 12; j++) {
            int u = tid + j * 256;       // 0..3071 float4 units
            uint32_t sa;
            const float* gp;
            if (u < 1024) {              // A: 128 rows x 8 float4
                int r = u >> 3, c16 = u & 7;
                sa = base + r * (RST*4) + c16 * 16;
                gp = A + (size_t)(bm + r) * GK + kc * BK + c16 * 4;
            } else {                     // B: 256 rows x 8 float4
                int uu = u - 1024;
                int r = uu >> 3, c16 = uu & 7;
                sa = base + ATILEB + r * (RST*4) + c16 * 16;
                gp = Bp + (size_t)(nb + r) * GK + kc * BK + c16 * 4;
            }
            asm volatile("cp.async.cg.shared.global [%0], [%1], 16;"
                         :: "r"(sa), "l"(gp));
        }
        asm volatile("cp.async.commit_group;" ::: "memory");
    };

    load_chunk(0, 0);

    for (int t = 0; t < NCH; t++) {
        const int s = t & 1;
        if (t + 1 < NCH) {
            load_chunk(t + 1, (t + 1) & 1);
            asm volatile("cp.async.wait_group 1;" ::: "memory");
        } else {
            asm volatile("cp.async.wait_group 0;" ::: "memory");
        }
        __syncthreads();

        const float* Ab = sm + s * (STAGEB/4);
        const float* Bb = Ab + ATILEB/4;
#pragma unroll
        for (int ks = 0; ks < 4; ks++) {
            const int k0 = ks * 8;
            uint32_t af[4][4], bf[8][2];
#pragma unroll
            for (int tm = 0; tm < 4; tm++) {
                const int m0 = wm + tm * 16;
                af[tm][0] = rnau(Ab[(m0 + g)     * RST + k0 + tg]);
                af[tm][1] = rnau(Ab[(m0 + g + 8) * RST + k0 + tg]);
                af[tm][2] = rnau(Ab[(m0 + g)     * RST + k0 + tg + 4]);
                af[tm][3] = rnau(Ab[(m0 + g + 8) * RST + k0 + tg + 4]);
            }
#pragma unroll
            for (int tn = 0; tn < 8; tn++) {
                const int n0 = wn + tn * 8;
                bf[tn][0] = rnau(Bb[(n0 + g) * RST + k0 + tg]);
                bf[tn][1] = rnau(Bb[(n0 + g) * RST + k0 + tg + 4]);
            }
#pragma unroll
            for (int tm = 0; tm < 4; tm++)
#pragma unroll
                for (int tn = 0; tn < 8; tn++)
                    mma_tf32(c[tm][tn], af[tm], bf[tn]);
        }
        __syncthreads();
    }

    // Epilogue: direct register -> global
#pragma unroll
    for (int tm = 0; tm < 4; tm++) {
        const int row0 = bm + wm + tm * 16 + g;
#pragma unroll
        for (int tn = 0; tn < 8; tn++) {
            const int col = nb + wn + tn * 8 + tg * 2;
            *(float2*)&Cp[(size_t)row0 * ldc + col] =
                make_float2(c[tm][tn][0], c[tm][tn][1]);
            *(float2*)&Cp[(size_t)(row0 + 8) * ldc + col] =
                make_float2(c[tm][tn][2], c[tm][tn][3]);
        }
    }
}

// ---------------------------------------------------------------------------
// RoPE (in-place)
// ---------------------------------------------------------------------------
__global__ void rope_kernel(float* __restrict__ x, const float* __restrict__ cs,
                            const float* __restrict__ sn, int nheads, int total) {
    int idx = blockIdx.x * blockDim.x + threadIdx.x;
    if (idx >= total) return;
    int d  = idx & 31;
    int h  = (idx >> 5) % nheads;
    int bt = idx / (32 * nheads);
    int t  = bt & (TT - 1);
    float* row = x + (size_t)bt * (nheads * HD) + h * HD;
    float x1 = row[d], x2 = row[d + 32];
    float c1 = cs[t * HD + d],      s1 = sn[t * HD + d];
    float c2 = cs[t * HD + d + 32], s2 = sn[t * HD + d + 32];
    row[d]      = x1 * c1 - x2 * s1;
    row[d + 32] = x2 * c2 + x1 * s2;
}

// ---------------------------------------------------------------------------
// Tensor-core flash attention (tf32 mma.sync), causal, GQA
// (unchanged from R4-passing version)
// ---------------------------------------------------------------------------
#define KST 68
#define VST 72
#define ATTN_SMEM ((64*KST + 64*VST + 64*KST) * 4)

__global__ __launch_bounds__(128) void attn_tc(const float* __restrict__ q,
                                               const float* __restrict__ k,
                                               const float* __restrict__ v,
                                               float* __restrict__ o) {
    const int qt = (int)gridDim.x - 1 - (int)blockIdx.x;
    const int h  = blockIdx.y;
    const int b  = blockIdx.z;
    const int kvh = h >> 2;
    const int q0 = qt * 64;

    extern __shared__ float sm[];
    float* Ks = sm;
    float* Vs = Ks + 64 * KST;
    float* Ps = Vs + 64 * VST;

    const int tid = threadIdx.x;
    const int w = tid >> 5, lane = tid & 31;
    const int g = lane >> 2, tg = lane & 3;
    const int wq0 = w * 16;

#pragma unroll
    for (int j = 0; j < 8; j++) {
        int i = tid + j * 128;
        int r = i >> 4, c4 = i & 15;
        float4 qv = *(const float4*)&q[(size_t)(b * TT + q0 + r) * QN + h * HD + c4 * 4];
        *(float4*)&Ks[r * KST + c4 * 4] =
            make_float4(rna(qv.x), rna(qv.y), rna(qv.z), rna(qv.w));
    }
    __syncthreads();

    uint32_t qf[8][4];
#pragma unroll
    for (int ks = 0; ks < 8; ks++) {
        const int k0 = ks * 8;
        qf[ks][0] = __float_as_uint(Ks[(wq0 + g)     * KST + k0 + tg]);
        qf[ks][1] = __float_as_uint(Ks[(wq0 + g + 8) * KST + k0 + tg]);
        qf[ks][2] = __float_as_uint(Ks[(wq0 + g)     * KST + k0 + tg + 4]);
        qf[ks][3] = __float_as_uint(Ks[(wq0 + g + 8) * KST + k0 + tg + 4]);
    }

    float oacc[8][4];
#pragma unroll
    for (int nt = 0; nt < 8; nt++)
#pragma unroll
        for (int qq = 0; qq < 4; qq++) oacc[nt][qq] = 0.f;
    float m0 = -INFINITY, m1 = -INFINITY, l0 = 0.f, l1 = 0.f;

    for (int kt = 0; kt <= qt; ++kt) {
        __syncthreads();
        const int k0g = kt * 64;
#pragma unroll
        for (int j = 0; j < 8; j++) {
            int i = tid + j * 128;
            int r = i >> 4, c4 = i & 15;
            size_t base = (size_t)(b * TT + k0g + r) * KN + kvh * HD + c4 * 4;
            float4 kv4 = *(const float4*)&k[base];
            float4 vv4 = *(const float4*)&v[base];
            *(float4*)&Ks[r * KST + c4 * 4] =
                make_float4(rna(kv4.x), rna(kv4.y), rna(kv4.z), rna(kv4.w));
            *(float4*)&Vs[r * VST + c4 * 4] =
                make_float4(rna(vv4.x), rna(vv4.y), rna(vv4.z), rna(vv4.w));
        }
        __syncthreads();

        float sc[8][4];
#pragma unroll
        for (int nt = 0; nt < 8; nt++)
#pragma unroll
            for (int qq = 0; qq < 4; qq++) sc[nt][qq] = 0.f;

#pragma unroll
        for (int ks = 0; ks < 8; ks++) {
            const int k0 = ks * 8;
            uint32_t bf[8][2];
#pragma unroll
            for (int nt = 0; nt < 8; nt++) {
                bf[nt][0] = __float_as_uint(Ks[(nt * 8 + g) * KST + k0 + tg]);
                bf[nt][1] = __float_as_uint(Ks[(nt * 8 + g) * KST + k0 + tg + 4]);
            }
#pragma unroll
            for (int nt = 0; nt < 8; nt++)
                mma_tf32(sc[nt], qf[ks], bf[nt]);
        }

        const float scale = 0.125f;
        if (kt == qt) {
            const int r0 = wq0 + g, r1 = wq0 + g + 8;
#pragma unroll
            for (int nt = 0; nt < 8; nt++) {
                int c0 = nt * 8 + 2 * tg, c1 = c0 + 1;
                sc[nt][0] = (c0 <= r0) ? sc[nt][0] * scale : -1e30f;
                sc[nt][1] = (c1 <= r0) ? sc[nt][1] * scale : -1e30f;
                sc[nt][2] = (c0 <= r1) ? sc[nt][2] * scale : -1e30f;
                sc[nt][3] = (c1 <= r1) ? sc[nt][3] * scale : -1e30f;
            }
        } else {
#pragma unroll
            for (int nt = 0; nt < 8; nt++)
#pragma unroll
                for (int qq = 0; qq < 4; qq++) sc[nt][qq] *= scale;
        }

        float mx0 = -INFINITY, mx1 = -INFINITY;
#pragma unroll
        for (int nt = 0; nt < 8; nt++) {
            mx0 = fmaxf(mx0, fmaxf(sc[nt][0], sc[nt][1]));
            mx1 = fmaxf(mx1, fmaxf(sc[nt][2], sc[nt][3]));
        }
        mx0 = fmaxf(mx0, __shfl_xor_sync(0xffffffffu, mx0, 1));
        mx0 = fmaxf(mx0, __shfl_xor_sync(0xffffffffu, mx0, 2));
        mx1 = fmaxf(mx1, __shfl_xor_sync(0xffffffffu, mx1, 1));
        mx1 = fmaxf(mx1, __shfl_xor_sync(0xffffffffu, mx1, 2));

        float mn0 = fmaxf(m0, mx0), mn1 = fmaxf(m1, mx1);
        float al0 = __expf(m0 - mn0), al1 = __expf(m1 - mn1);
        m0 = mn0; m1 = mn1;
        float rs0 = 0.f, rs1 = 0.f;
#pragma unroll
        for (int nt = 0; nt < 8; nt++) {
            sc[nt][0] = __expf(sc[nt][0] - mn0);
            sc[nt][1] = __expf(sc[nt][1] - mn0);
            sc[nt][2] = __expf(sc[nt][2] - mn1);
            sc[nt][3] = __expf(sc[nt][3] - mn1);
            rs0 += sc[nt][0] + sc[nt][1];
            rs1 += sc[nt][2] + sc[nt][3];
        }
        rs0 += __shfl_xor_sync(0xffffffffu, rs0, 1);
        rs0 += __shfl_xor_sync(0xffffffffu, rs0, 2);
        rs1 += __shfl_xor_sync(0xffffffffu, rs1, 1);
        rs1 += __shfl_xor_sync(0xffffffffu, rs1, 2);
        l0 = l0 * al0 + rs0;
        l1 = l1 * al1 + rs1;
#pragma unroll
        for (int nt = 0; nt < 8; nt++) {
            oacc[nt][0] *= al0; oacc[nt][1] *= al0;
            oacc[nt][2] *= al1; oacc[nt][3] *= al1;
        }

#pragma unroll
        for (int nt = 0; nt < 8; nt++) {
            *(float2*)&Ps[(wq0 + g)     * KST + nt * 8 + 2 * tg] =
                make_float2(sc[nt][0], sc[nt][1]);
            *(float2*)&Ps[(wq0 + g + 8) * KST + nt * 8 + 2 * tg] =
                make_float2(sc[nt][2], sc[nt][3]);
        }
        __syncwarp();

#pragma unroll
        for (int ks = 0; ks < 8; ks++) {
            const int kk = ks * 8;
            uint32_t af[4];
            af[0] = __float_as_uint(Ps[(wq0 + g)     * KST + kk + tg]);
            af[1] = __float_as_uint(Ps[(wq0 + g + 8) * KST + kk + tg]);
            af[2] = __float_as_uint(Ps[(wq0 + g)     * KST + kk + tg + 4]);
            af[3] = __float_as_uint(Ps[(wq0 + g + 8) * KST + kk + tg + 4]);
            uint32_t bf[8][2];
#pragma unroll
            for (int nt = 0; nt < 8; nt++) {
                bf[nt][0] = __float_as_uint(Vs[(kk + tg)     * VST + nt * 8 + g]);
                bf[nt][1] = __float_as_uint(Vs[(kk + tg + 4) * VST + nt * 8 + g]);
            }
#pragma unroll
            for (int nt = 0; nt < 8; nt++)
                mma_tf32(oacc[nt], af, bf[nt]);
        }
    }

    const float inv0 = 1.f / l0, inv1 = 1.f / l1;
    const int row0 = b * TT + q0 + wq0 + g;
#pragma unroll
    for (int nt = 0; nt < 8; nt++) {
        const int col = h * HD + nt * 8 + 2 * tg;
        *(float2*)&o[(size_t)row0 * QN + col] =
            make_float2(oacc[nt][0] * inv0, oacc[nt][1] * inv0);
        *(float2*)&o[(size_t)(row0 + 8) * QN + col] =
            make_float2(oacc[nt][2] * inv1, oacc[nt][3] * inv1);
    }
}

// ---------------------------------------------------------------------------
// Launcher
// ---------------------------------------------------------------------------
extern "C" void kernel_launch(void* const* d_in, const int* in_sizes, int n_in,
                              void* d_out, int out_size) {
    const float* x   = (const float*)d_in[0];
    const float* cs  = (const float*)d_in[1];
    const float* sn  = (const float*)d_in[2];
    const float* Wq  = (const float*)d_in[3];
    const float* Wk  = (const float*)d_in[4];
    const float* Wv  = (const float*)d_in[5];
    const float* Wo  = (const float*)d_in[6];
    float* out = (float*)d_out;

    float *q_ptr, *k_ptr, *v_ptr, *att_ptr;
    cudaGetSymbolAddress((void**)&q_ptr,  g_q);
    cudaGetSymbolAddress((void**)&k_ptr,  g_k);
    cudaGetSymbolAddress((void**)&v_ptr,  g_v);
    cudaGetSymbolAddress((void**)&att_ptr, g_att);

    cudaFuncSetAttribute(gemm_mma, cudaFuncAttributeMaxDynamicSharedMemorySize, GEMM_SMEM);
    cudaFuncSetAttribute(attn_tc,  cudaFuncAttributeMaxDynamicSharedMemorySize, ATTN_SMEM);

    // Fused QKV projection: N = 2048 + 512 + 512 = 3072
    gemm_mma<<<dim3(3072/BN, MROWS/BM), 256, GEMM_SMEM>>>(
        x, Wq, Wk, Wv, q_ptr, k_ptr, v_ptr, 2048, 2560, QN);

    // RoPE on q and k
    {
        int totq = BB * TT * NH * 32;
        rope_kernel<<<(totq + 255) / 256, 256>>>(q_ptr, cs, sn, NH, totq);
        int totk = BB * TT * NKV * 32;
        rope_kernel<<<(totk + 255) / 256, 256>>>(k_ptr, cs, sn, NKV, totk);
    }

    // Tensor-core flash attention
    attn_tc<<<dim3(TT / 64, NH, BB), 128, ATTN_SMEM>>>(q_ptr, k_ptr, v_ptr, att_ptr);

    // Output projection (seg 0 only)
    gemm_mma<<<dim3(DM/BN, MROWS/BM), 256, GEMM_SMEM>>>(
        att_ptr, Wo, Wo, Wo, out, out, out, DM, DM + 512, DM);
}

// round 6
// speedup vs baseline: 3.4252x; 1.0540x over previous
#include <cuda_runtime.h>
#include <cuda_bf16.h>
#include <math.h>
#include <stdint.h>

// Problem constants
#define BB 2
#define TT 2048
#define DM 2048
#define NH 32
#define NKV 8
#define HD 64
#define MROWS (BB*TT)          // 4096
#define QN (NH*HD)             // 2048
#define KN (NKV*HD)            // 512
#define GK DM                  // K dim of every GEMM = 2048

// Scratch (device globals — allocation-free)
__device__ float g_q[MROWS*QN];
__device__ float g_k[MROWS*KN];
__device__ float g_v[MROWS*KN];
__device__ float g_att[MROWS*QN];
__device__ float g_xc[MROWS*DM];
__device__ float g_wqc[QN*DM];
__device__ float g_wkc[KN*DM];
__device__ float g_wvc[KN*DM];
__device__ float g_woc[DM*QN];

__device__ __forceinline__ float rna(float x) {
    uint32_t u;
    asm("cvt.rna.tf32.f32 %0, %1;" : "=r"(u) : "f"(x));
    return __uint_as_float(u);
}
__device__ __forceinline__ uint32_t smem_u32(const void* p) {
    uint32_t a;
    asm("{ .reg .u64 t; cvta.to.shared.u64 t, %1; cvt.u32.u64 %0, t; }"
        : "=r"(a) : "l"(p));
    return a;
}
__device__ __forceinline__ void mma_tf32(float c[4], const uint32_t a[4],
                                         const uint32_t b[2]) {
    asm volatile(
        "mma.sync.aligned.m16n8k8.row.col.f32.tf32.tf32.f32 "
        "{%0,%1,%2,%3}, {%4,%5,%6,%7}, {%8,%9}, {%0,%1,%2,%3};"
        : "+f"(c[0]), "+f"(c[1]), "+f"(c[2]), "+f"(c[3])
        : "r"(a[0]), "r"(a[1]), "r"(a[2]), "r"(a[3]), "r"(b[0]), "r"(b[1]));
}

// ---------------------------------------------------------------------------
// tf32 rounding pass
// ---------------------------------------------------------------------------
__global__ void cvt_tf32(const float* __restrict__ in, float* __restrict__ out, int n4) {
    int i = blockIdx.x * blockDim.x + threadIdx.x;
    if (i >= n4) return;
    float4 v = ((const float4*)in)[i];
    ((float4*)out)[i] = make_float4(rna(v.x), rna(v.y), rna(v.z), rna(v.w));
}

// ---------------------------------------------------------------------------
// mma.sync tf32 NT GEMM, BM=128, BN=256, BK=32, 256 threads.
// Inputs pre-rounded to tf32; fragment loads are plain LDS.
// Segmented-N for fused QKV (see R5).
// ---------------------------------------------------------------------------
#define BM 128
#define BN 256
#define BK 32
#define NCH (GK/BK)            // 64
#define RST 36
#define ATILEB (128*RST*4)
#define STAGEB ((128+256)*RST*4)
#define GEMM_SMEM (2*STAGEB)   // 110592 B

__global__ __launch_bounds__(256, 1) void gemm_mma(
    const float* __restrict__ A,
    const float* __restrict__ B0, const float* __restrict__ B1,
    const float* __restrict__ B2,
    float* __restrict__ C0, float* __restrict__ C1, float* __restrict__ C2,
    int nb1, int nb2, int ld0) {
    extern __shared__ float sm[];
    const int tid = threadIdx.x;
    const int bm = blockIdx.y * BM;
    const int bn = blockIdx.x * BN;
    const int wid = tid >> 5, lane = tid & 31;
    const int g = lane >> 2, tg = lane & 3;
    const int wm = (wid >> 2) * 64;
    const int wn = (wid & 3) * 64;

    const float* Bp; float* Cp; int nb, ldc;
    if (bn < nb1)      { Bp = B0; Cp = C0; nb = bn;       ldc = ld0; }
    else if (bn < nb2) { Bp = B1; Cp = C1; nb = bn - nb1; ldc = 512; }
    else               { Bp = B2; Cp = C2; nb = bn - nb2; ldc = 512; }

    float c[4][8][4];
#pragma unroll
    for (int i = 0; i < 4; i++)
#pragma unroll
        for (int j = 0; j < 8; j++)
#pragma unroll
            for (int q = 0; q < 4; q++) c[i][j][q] = 0.f;

    const uint32_t sb = smem_u32(sm);

    auto load_chunk = [&](int kc, int s) {
        uint32_t base = sb + s * STAGEB;
#pragma unroll
        for (int j = 0; j < 12; j++) {
            int u = tid + j * 256;
            uint32_t sa;
            const float* gp;
            if (u < 1024) {
                int r = u >> 3, c16 = u & 7;
                sa = base + r * (RST*4) + c16 * 16;
                gp = A + (size_t)(bm + r) * GK + kc * BK + c16 * 4;
            } else {
                int uu = u - 1024;
                int r = uu >> 3, c16 = uu & 7;
                sa = base + ATILEB + r * (RST*4) + c16 * 16;
                gp = Bp + (size_t)(nb + r) * GK + kc * BK + c16 * 4;
            }
            asm volatile("cp.async.cg.shared.global [%0], [%1], 16;"
                         :: "r"(sa), "l"(gp));
        }
        asm volatile("cp.async.commit_group;" ::: "memory");
    };

    load_chunk(0, 0);

    for (int t = 0; t < NCH; t++) {
        const int s = t & 1;
        if (t + 1 < NCH) {
            load_chunk(t + 1, (t + 1) & 1);
            asm volatile("cp.async.wait_group 1;" ::: "memory");
        } else {
            asm volatile("cp.async.wait_group 0;" ::: "memory");
        }
        __syncthreads();

        const float* Ab = sm + s * (STAGEB/4);
        const float* Bb = Ab + ATILEB/4;
#pragma unroll
        for (int ks = 0; ks < 4; ks++) {
            const int k0 = ks * 8;
            uint32_t af[4][4], bf[8][2];
#pragma unroll
            for (int tm = 0; tm < 4; tm++) {
                const int m0 = wm + tm * 16;
                af[tm][0] = __float_as_uint(Ab[(m0 + g)     * RST + k0 + tg]);
                af[tm][1] = __float_as_uint(Ab[(m0 + g + 8) * RST + k0 + tg]);
                af[tm][2] = __float_as_uint(Ab[(m0 + g)     * RST + k0 + tg + 4]);
                af[tm][3] = __float_as_uint(Ab[(m0 + g + 8) * RST + k0 + tg + 4]);
            }
#pragma unroll
            for (int tn = 0; tn < 8; tn++) {
                const int n0 = wn + tn * 8;
                bf[tn][0] = __float_as_uint(Bb[(n0 + g) * RST + k0 + tg]);
                bf[tn][1] = __float_as_uint(Bb[(n0 + g) * RST + k0 + tg + 4]);
            }
#pragma unroll
            for (int tm = 0; tm < 4; tm++)
#pragma unroll
                for (int tn = 0; tn < 8; tn++)
                    mma_tf32(c[tm][tn], af[tm], bf[tn]);
        }
        __syncthreads();
    }

#pragma unroll
    for (int tm = 0; tm < 4; tm++) {
        const int row0 = bm + wm + tm * 16 + g;
#pragma unroll
        for (int tn = 0; tn < 8; tn++) {
            const int col = nb + wn + tn * 8 + tg * 2;
            *(float2*)&Cp[(size_t)row0 * ldc + col] =
                make_float2(c[tm][tn][0], c[tm][tn][1]);
            *(float2*)&Cp[(size_t)(row0 + 8) * ldc + col] =
                make_float2(c[tm][tn][2], c[tm][tn][3]);
        }
    }
}

// ---------------------------------------------------------------------------
// RoPE (in-place)
// ---------------------------------------------------------------------------
__global__ void rope_kernel(float* __restrict__ x, const float* __restrict__ cs,
                            const float* __restrict__ sn, int nheads, int total) {
    int idx = blockIdx.x * blockDim.x + threadIdx.x;
    if (idx >= total) return;
    int d  = idx & 31;
    int h  = (idx >> 5) % nheads;
    int bt = idx / (32 * nheads);
    int t  = bt & (TT - 1);
    float* row = x + (size_t)bt * (nheads * HD) + h * HD;
    float x1 = row[d], x2 = row[d + 32];
    float c1 = cs[t * HD + d],      s1 = sn[t * HD + d];
    float c2 = cs[t * HD + d + 32], s2 = sn[t * HD + d + 32];
    row[d]      = x1 * c1 - x2 * s1;
    row[d + 32] = x2 * c2 + x1 * s2;
}

// ---------------------------------------------------------------------------
// Tensor-core flash attention v2 (tf32 mma.sync), causal, GQA
// Block: 128 threads (4 warps x 32 q-rows). Tiles: 128 q x 64 kv, HD=64.
// Each B-fragment feeds two A-fragments (lo/hi 16-row halves).
// Smem: Ks[64][68], Vs[64][72], Ps[128][68] = 70656 B.
// Output written tf32-rounded (consumed by O-proj GEMM directly).
// ---------------------------------------------------------------------------
#define KST 68
#define VST 72
#define ATTN_SMEM ((64*KST + 64*VST + 128*KST) * 4)

__global__ __launch_bounds__(128) void attn_tc(const float* __restrict__ q,
                                               const float* __restrict__ k,
                                               const float* __restrict__ v,
                                               float* __restrict__ o) {
    const int qt = (int)gridDim.x - 1 - (int)blockIdx.x;   // heavy CTAs first
    const int h  = blockIdx.y;
    const int b  = blockIdx.z;
    const int kvh = h >> 2;
    const int q0 = qt * 128;

    extern __shared__ float sm[];
    float* Ks = sm;                    // [64][KST]
    float* Vs = Ks + 64 * KST;         // [64][VST]
    float* Ps = Vs + 64 * VST;         // [128][KST]

    const int tid = threadIdx.x;
    const int w = tid >> 5, lane = tid & 31;
    const int g = lane >> 2, tg = lane & 3;
    const int wq0 = w * 32;

    // ---- Stage all 128 Q rows (rounded): rows 0-63 -> Ks, 64-127 -> Vs ----
#pragma unroll
    for (int j = 0; j < 16; j++) {
        int i = tid + j * 128;            // 0..2047 float4 units
        int r = i >> 4, c4 = i & 15;
        float4 qv = *(const float4*)&q[(size_t)(b * TT + q0 + r) * QN + h * HD + c4 * 4];
        float* dst = (r < 64) ? &Ks[r * KST + c4 * 4] : &Vs[(r - 64) * VST + c4 * 4];
        *(float4*)dst = make_float4(rna(qv.x), rna(qv.y), rna(qv.z), rna(qv.w));
    }
    __syncthreads();

    auto qrow = [&](int r) -> const float* {
        return (r < 64) ? &Ks[r * KST] : &Vs[(r - 64) * VST];
    };

    uint32_t qfl[8][4], qfh[8][4];
#pragma unroll
    for (int ks = 0; ks < 8; ks++) {
        const int k0 = ks * 8;
        qfl[ks][0] = __float_as_uint(qrow(wq0 + g)[k0 + tg]);
        qfl[ks][1] = __float_as_uint(qrow(wq0 + g + 8)[k0 + tg]);
        qfl[ks][2] = __float_as_uint(qrow(wq0 + g)[k0 + tg + 4]);
        qfl[ks][3] = __float_as_uint(qrow(wq0 + g + 8)[k0 + tg + 4]);
        qfh[ks][0] = __float_as_uint(qrow(wq0 + 16 + g)[k0 + tg]);
        qfh[ks][1] = __float_as_uint(qrow(wq0 + 24 + g)[k0 + tg]);
        qfh[ks][2] = __float_as_uint(qrow(wq0 + 16 + g)[k0 + tg + 4]);
        qfh[ks][3] = __float_as_uint(qrow(wq0 + 24 + g)[k0 + tg + 4]);
    }

    float oal[8][4], oah[8][4];
#pragma unroll
    for (int nt = 0; nt < 8; nt++)
#pragma unroll
        for (int qq = 0; qq < 4; qq++) { oal[nt][qq] = 0.f; oah[nt][qq] = 0.f; }
    float mrow[4] = {-INFINITY, -INFINITY, -INFINITY, -INFINITY};
    float lrow[4] = {0.f, 0.f, 0.f, 0.f};

    const int nkt = 2 * qt + 2;
    for (int kt = 0; kt < nkt; ++kt) {
        __syncthreads();                 // previous iter's Ks/Vs reads done
        const int k0g = kt * 64;
        // ---- Stage K,V (rounded) ----
#pragma unroll
        for (int j = 0; j < 8; j++) {
            int i = tid + j * 128;
            int r = i >> 4, c4 = i & 15;
            size_t base = (size_t)(b * TT + k0g + r) * KN + kvh * HD + c4 * 4;
            float4 kv4 = *(const float4*)&k[base];
            float4 vv4 = *(const float4*)&v[base];
            *(float4*)&Ks[r * KST + c4 * 4] =
                make_float4(rna(kv4.x), rna(kv4.y), rna(kv4.z), rna(kv4.w));
            *(float4*)&Vs[r * VST + c4 * 4] =
                make_float4(rna(vv4.x), rna(vv4.y), rna(vv4.z), rna(vv4.w));
        }
        __syncthreads();

        // ---- S = Q @ K^T (both halves share B-frags) ----
        float scl[8][4], sch[8][4];
#pragma unroll
        for (int nt = 0; nt < 8; nt++)
#pragma unroll
            for (int qq = 0; qq < 4; qq++) { scl[nt][qq] = 0.f; sch[nt][qq] = 0.f; }

#pragma unroll
        for (int ks = 0; ks < 8; ks++) {
            const int k0 = ks * 8;
            uint32_t bf[8][2];
#pragma unroll
            for (int nt = 0; nt < 8; nt++) {
                bf[nt][0] = __float_as_uint(Ks[(nt * 8 + g) * KST + k0 + tg]);
                bf[nt][1] = __float_as_uint(Ks[(nt * 8 + g) * KST + k0 + tg + 4]);
            }
#pragma unroll
            for (int nt = 0; nt < 8; nt++) {
                mma_tf32(scl[nt], qfl[ks], bf[nt]);
                mma_tf32(sch[nt], qfh[ks], bf[nt]);
            }
        }

        // ---- scale + causal mask ----
        const float scale = 0.125f;
        if (kt >= 2 * qt) {              // diagonal region
            const int r0 = q0 + wq0 + g,      r1 = r0 + 8;
            const int r2 = q0 + wq0 + 16 + g, r3 = r2 + 8;
#pragma unroll
            for (int nt = 0; nt < 8; nt++) {
                int c0 = k0g + nt * 8 + 2 * tg, c1 = c0 + 1;
                scl[nt][0] = (c0 <= r0) ? scl[nt][0] * scale : -1e30f;
                scl[nt][1] = (c1 <= r0) ? scl[nt][1] * scale : -1e30f;
                scl[nt][2] = (c0 <= r1) ? scl[nt][2] * scale : -1e30f;
                scl[nt][3] = (c1 <= r1) ? scl[nt][3] * scale : -1e30f;
                sch[nt][0] = (c0 <= r2) ? sch[nt][0] * scale : -1e30f;
                sch[nt][1] = (c1 <= r2) ? sch[nt][1] * scale : -1e30f;
                sch[nt][2] = (c0 <= r3) ? sch[nt][2] * scale : -1e30f;
                sch[nt][3] = (c1 <= r3) ? sch[nt][3] * scale : -1e30f;
            }
        } else {
#pragma unroll
            for (int nt = 0; nt < 8; nt++)
#pragma unroll
                for (int qq = 0; qq < 4; qq++) {
                    scl[nt][qq] *= scale; sch[nt][qq] *= scale;
                }
        }

        // ---- online softmax: 4 row-sets (lo:g,g+8 ; hi:16+g,24+g) ----
        float mx[4] = {-INFINITY, -INFINITY, -INFINITY, -INFINITY};
#pragma unroll
        for (int nt = 0; nt < 8; nt++) {
            mx[0] = fmaxf(mx[0], fmaxf(scl[nt][0], scl[nt][1]));
            mx[1] = fmaxf(mx[1], fmaxf(scl[nt][2], scl[nt][3]));
            mx[2] = fmaxf(mx[2], fmaxf(sch[nt][0], sch[nt][1]));
            mx[3] = fmaxf(mx[3], fmaxf(sch[nt][2], sch[nt][3]));
        }
#pragma unroll
        for (int r = 0; r < 4; r++) {
            mx[r] = fmaxf(mx[r], __shfl_xor_sync(0xffffffffu, mx[r], 1));
            mx[r] = fmaxf(mx[r], __shfl_xor_sync(0xffffffffu, mx[r], 2));
        }
        float al[4], rs[4] = {0.f, 0.f, 0.f, 0.f};
#pragma unroll
        for (int r = 0; r < 4; r++) {
            float mn = fmaxf(mrow[r], mx[r]);
            al[r] = __expf(mrow[r] - mn);
            mrow[r] = mn;
        }
#pragma unroll
        for (int nt = 0; nt < 8; nt++) {
            scl[nt][0] = __expf(scl[nt][0] - mrow[0]);
            scl[nt][1] = __expf(scl[nt][1] - mrow[0]);
            scl[nt][2] = __expf(scl[nt][2] - mrow[1]);
            scl[nt][3] = __expf(scl[nt][3] - mrow[1]);
            sch[nt][0] = __expf(sch[nt][0] - mrow[2]);
            sch[nt][1] = __expf(sch[nt][1] - mrow[2]);
            sch[nt][2] = __expf(sch[nt][2] - mrow[3]);
            sch[nt][3] = __expf(sch[nt][3] - mrow[3]);
            rs[0] += scl[nt][0] + scl[nt][1];
            rs[1] += scl[nt][2] + scl[nt][3];
            rs[2] += sch[nt][0] + sch[nt][1];
            rs[3] += sch[nt][2] + sch[nt][3];
        }
#pragma unroll
        for (int r = 0; r < 4; r++) {
            rs[r] += __shfl_xor_sync(0xffffffffu, rs[r], 1);
            rs[r] += __shfl_xor_sync(0xffffffffu, rs[r], 2);
            lrow[r] = lrow[r] * al[r] + rs[r];
        }
#pragma unroll
        for (int nt = 0; nt < 8; nt++) {
            oal[nt][0] *= al[0]; oal[nt][1] *= al[0];
            oal[nt][2] *= al[1]; oal[nt][3] *= al[1];
            oah[nt][0] *= al[2]; oah[nt][1] *= al[2];
            oah[nt][2] *= al[3]; oah[nt][3] *= al[3];
        }

        // ---- P to smem (warp-private rows), reload as A-frags ----
#pragma unroll
        for (int nt = 0; nt < 8; nt++) {
            *(float2*)&Ps[(wq0 + g)      * KST + nt * 8 + 2 * tg] =
                make_float2(scl[nt][0], scl[nt][1]);
            *(float2*)&Ps[(wq0 + g + 8)  * KST + nt * 8 + 2 * tg] =
                make_float2(scl[nt][2], scl[nt][3]);
            *(float2*)&Ps[(wq0 + g + 16) * KST + nt * 8 + 2 * tg] =
                make_float2(sch[nt][0], sch[nt][1]);
            *(float2*)&Ps[(wq0 + g + 24) * KST + nt * 8 + 2 * tg] =
                make_float2(sch[nt][2], sch[nt][3]);
        }
        __syncwarp();

        // ---- O += P @ V (both halves share B-frags) ----
#pragma unroll
        for (int ks = 0; ks < 8; ks++) {
            const int kk = ks * 8;
            uint32_t afl[4], afh[4];
            afl[0] = __float_as_uint(Ps[(wq0 + g)      * KST + kk + tg]);
            afl[1] = __float_as_uint(Ps[(wq0 + g + 8)  * KST + kk + tg]);
            afl[2] = __float_as_uint(Ps[(wq0 + g)      * KST + kk + tg + 4]);
            afl[3] = __float_as_uint(Ps[(wq0 + g + 8)  * KST + kk + tg + 4]);
            afh[0] = __float_as_uint(Ps[(wq0 + g + 16) * KST + kk + tg]);
            afh[1] = __float_as_uint(Ps[(wq0 + g + 24) * KST + kk + tg]);
            afh[2] = __float_as_uint(Ps[(wq0 + g + 16) * KST + kk + tg + 4]);
            afh[3] = __float_as_uint(Ps[(wq0 + g + 24) * KST + kk + tg + 4]);
            uint32_t bf[8][2];
#pragma unroll
            for (int nt = 0; nt < 8; nt++) {
                bf[nt][0] = __float_as_uint(Vs[(kk + tg)     * VST + nt * 8 + g]);
                bf[nt][1] = __float_as_uint(Vs[(kk + tg + 4) * VST + nt * 8 + g]);
            }
#pragma unroll
            for (int nt = 0; nt < 8; nt++) {
                mma_tf32(oal[nt], afl, bf[nt]);
                mma_tf32(oah[nt], afh, bf[nt]);
            }
        }
    }

    // ---- normalize + write (tf32-rounded: feeds O-proj GEMM directly) ----
    float inv[4];
#pragma unroll
    for (int r = 0; r < 4; r++) inv[r] = 1.f / lrow[r];
    const int rb = b * TT + q0 + wq0 + g;
#pragma unroll
    for (int nt = 0; nt < 8; nt++) {
        const int col = h * HD + nt * 8 + 2 * tg;
        *(float2*)&o[(size_t)rb * QN + col] =
            make_float2(rna(oal[nt][0] * inv[0]), rna(oal[nt][1] * inv[0]));
        *(float2*)&o[(size_t)(rb + 8) * QN + col] =
            make_float2(rna(oal[nt][2] * inv[1]), rna(oal[nt][3] * inv[1]));
        *(float2*)&o[(size_t)(rb + 16) * QN + col] =
            make_float2(rna(oah[nt][0] * inv[2]), rna(oah[nt][1] * inv[2]));
        *(float2*)&o[(size_t)(rb + 24) * QN + col] =
            make_float2(rna(oah[nt][2] * inv[3]), rna(oah[nt][3] * inv[3]));
    }
}

// ---------------------------------------------------------------------------
// Launcher
// ---------------------------------------------------------------------------
extern "C" void kernel_launch(void* const* d_in, const int* in_sizes, int n_in,
                              void* d_out, int out_size) {
    const float* x   = (const float*)d_in[0];
    const float* cs  = (const float*)d_in[1];
    const float* sn  = (const float*)d_in[2];
    const float* Wq  = (const float*)d_in[3];
    const float* Wk  = (const float*)d_in[4];
    const float* Wv  = (const float*)d_in[5];
    const float* Wo  = (const float*)d_in[6];
    float* out = (float*)d_out;

    float *q_ptr, *k_ptr, *v_ptr, *att_ptr;
    float *xc, *wqc, *wkc, *wvc, *woc;
    cudaGetSymbolAddress((void**)&q_ptr,  g_q);
    cudaGetSymbolAddress((void**)&k_ptr,  g_k);
    cudaGetSymbolAddress((void**)&v_ptr,  g_v);
    cudaGetSymbolAddress((void**)&att_ptr, g_att);
    cudaGetSymbolAddress((void**)&xc,   g_xc);
    cudaGetSymbolAddress((void**)&wqc,  g_wqc);
    cudaGetSymbolAddress((void**)&wkc,  g_wkc);
    cudaGetSymbolAddress((void**)&wvc,  g_wvc);
    cudaGetSymbolAddress((void**)&woc,  g_woc);

    cudaFuncSetAttribute(gemm_mma, cudaFuncAttributeMaxDynamicSharedMemorySize, GEMM_SMEM);
    cudaFuncSetAttribute(attn_tc,  cudaFuncAttributeMaxDynamicSharedMemorySize, ATTN_SMEM);

    // Pre-round inputs once (numerically identical to in-loop rounding)
    {
        int n4;
        n4 = MROWS*DM/4;  cvt_tf32<<<(n4+255)/256, 256>>>(x,  xc,  n4);
        n4 = QN*DM/4;     cvt_tf32<<<(n4+255)/256, 256>>>(Wq, wqc, n4);
        n4 = KN*DM/4;     cvt_tf32<<<(n4+255)/256, 256>>>(Wk, wkc, n4);
        n4 = KN*DM/4;     cvt_tf32<<<(n4+255)/256, 256>>>(Wv, wvc, n4);
        n4 = DM*QN/4;     cvt_tf32<<<(n4+255)/256, 256>>>(Wo, woc, n4);
    }

    // Fused QKV projection: N = 2048 + 512 + 512 = 3072
    gemm_mma<<<dim3(3072/BN, MROWS/BM), 256, GEMM_SMEM>>>(
        xc, wqc, wkc, wvc, q_ptr, k_ptr, v_ptr, 2048, 2560, QN);

    // RoPE on q and k
    {
        int totq = BB * TT * NH * 32;
        rope_kernel<<<(totq + 255) / 256, 256>>>(q_ptr, cs, sn, NH, totq);
        int totk = BB * TT * NKV * 32;
        rope_kernel<<<(totk + 255) / 256, 256>>>(k_ptr, cs, sn, NKV, totk);
    }

    // Tensor-core flash attention (q-tile 128)
    attn_tc<<<dim3(TT / 128, NH, BB), 128, ATTN_SMEM>>>(q_ptr, k_ptr, v_ptr, att_ptr);

    // Output projection (seg 0 only; A = rounded attn output)
    gemm_mma<<<dim3(DM/BN, MROWS/BM), 256, GEMM_SMEM>>>(
        att_ptr, woc, woc, woc, out, out, out, DM, DM + 512, DM);
}